// round 14
// baseline (speedup 1.0000x reference)
#include <cuda_runtime.h>
#include <cuda_bf16.h>
#include <cstdint>
#include <math.h>

// ---------------- problem constants ----------------
#define BATCH 4
#define CIN   256
#define HH    128
#define WW    128
#define NANCH 9
#define NPIX  (HH*WW)         // 16384
#define NSC   (NPIX*NANCH)    // 147456 per image
#define PRE_K 600
#define POST_K 100
#define NMS_T 0.7f
#define MASKW 19              // ceil(600/32)

#define FSZ ((size_t)BATCH*NPIX*CIN)     // 16777216 elems per split
#define WSZ ((size_t)256*9*256)          // 589824 elems per split

// ---------------- device scratch (static; no allocations) ----------------
__device__ __align__(16) __nv_bfloat16 g_fs[2*FSZ];               // features NHWC, bf16 x2 splits
__device__ __align__(16) __nv_bfloat16 g_ts[2*FSZ];               // conv out NHWC, bf16 x2 splits
__device__ __align__(16) __nv_bfloat16 g_wb[2*WSZ];               // conv weights [s][oc][tap][ci]
__device__ __align__(16) __nv_bfloat16 g_hwb[2*48*256];           // head weights [s][o][k] bf16
__device__ float g_hb[48];
__device__ __align__(16) float g_anch[NANCH*4];
__device__ __align__(16) float g_scores[BATCH*NSC];
__device__ __align__(16) float g_deltas[(size_t)BATCH*NSC*4];
__device__ unsigned g_h16[BATCH*65536];
__device__ unsigned g_cG[BATCH], g_cE[BATCH], g_T16[BATCH];
__device__ __align__(16) unsigned long long g_candG[BATCH*1024];
__device__ __align__(16) unsigned long long g_candE[BATCH*1024];
__device__ __align__(16) float g_boxes[BATCH*PRE_K*4];
__device__ unsigned g_mask[BATCH*PRE_K*MASKW];

// ---------------- small helpers ----------------
__device__ __forceinline__ unsigned okey(float f) {
    unsigned u = __float_as_uint(f);
    return (u & 0x80000000u) ? ~u : (u | 0x80000000u);
}
__device__ __forceinline__ float dimval(const int* p) {
    int raw = *p;
    if (raw > 0 && raw < 1000000) return (float)raw;
    return __int_as_float(raw);
}
__device__ __forceinline__ uint32_t smem_u32(const void* p) {
    uint32_t a;
    asm("{ .reg .u64 t; cvta.to.shared.u64 t, %1; cvt.u32.u64 %0, t; }" : "=r"(a) : "l"(p));
    return a;
}
__device__ __forceinline__ void split2(float v, __nv_bfloat16& h1, __nv_bfloat16& h2) {
    h1 = __float2bfloat16_rn(v);
    h2 = __float2bfloat16_rn(v - __bfloat162float(h1));
}

#define LDMX4(r0,r1,r2,r3,addr) \
    asm volatile("ldmatrix.sync.aligned.m8n8.x4.shared.b16 {%0,%1,%2,%3}, [%4];" \
        : "=r"(r0), "=r"(r1), "=r"(r2), "=r"(r3) : "r"(addr))

#define MMA16816(d,a,b) \
    asm volatile("mma.sync.aligned.m16n8k16.row.col.f32.bf16.bf16.f32 " \
        "{%0,%1,%2,%3}, {%4,%5,%6,%7}, {%8,%9}, {%0,%1,%2,%3};" \
        : "+f"((d)[0]), "+f"((d)[1]), "+f"((d)[2]), "+f"((d)[3]) \
        : "r"((a)[0]), "r"((a)[1]), "r"((a)[2]), "r"((a)[3]), "r"((b)[0]), "r"((b)[1]))

#define CP_ASYNC16(daddr, gptr, sz) \
    asm volatile("cp.async.cg.shared.global [%0], [%1], 16, %2;" \
        :: "r"(daddr), "l"(gptr), "r"(sz))
#define CP_COMMIT() asm volatile("cp.async.commit_group;" ::: "memory")
#define CP_WAIT0()  asm volatile("cp.async.wait_group 0;" ::: "memory")

// ---------------- prep: conv weights + head weights + bias + anchors ----------------
__global__ void prep_wh(const float* __restrict__ cw,
                        const float* __restrict__ clw, const float* __restrict__ clb,
                        const float* __restrict__ bw,  const float* __restrict__ bb)
{
    int i = blockIdx.x * 256 + threadIdx.x;
    if (i < (int)WSZ) {
        int oc = i / 2304; int r = i - oc*2304; int tap = r >> 8; int ci = r & 255;
        float v = cw[(oc*256 + ci)*9 + tap];
        __nv_bfloat16 h1, h2; split2(v, h1, h2);
        g_wb[i] = h1; g_wb[WSZ + i] = h2;
        return;
    }
    i -= (int)WSZ;
    if (i < 48*256) {
        int o = i >> 8; int k = i & 255;
        float v = 0.f;
        if (o < 9) v = clw[o*256 + k];
        else if (o < 45) v = bw[(o-9)*256 + k];
        __nv_bfloat16 h1, h2; split2(v, h1, h2);
        g_hwb[i] = h1; g_hwb[48*256 + i] = h2;
        return;
    }
    i -= 48*256;
    if (i < 48) {
        float v = 0.f;
        if (i < 9) v = clb[i]; else if (i < 45) v = bb[i-9];
        g_hb[i] = v;
        return;
    }
    i -= 48;
    if (i < 36) {
        int a = i >> 2, c = i & 3;
        int si = a / 3, ri = a - si*3;
        double sc = (si == 0) ? 8.0 : (si == 1) ? 16.0 : 32.0;
        double rt = (ri == 0) ? 0.5 : (ri == 1) ? 1.0 : 2.0;
        double w = 16.0 * sc * sqrt(rt);
        double h = 16.0 * sc / sqrt(rt);
        double v = (c == 0) ? (-w*0.5) : (c == 1) ? (-h*0.5) : (c == 2) ? (w*0.5) : (h*0.5);
        g_anch[i] = (float)v;
    }
}

// ---------------- prep: feature NCHW fp32 -> NHWC bf16 x2 (vectorized stores) ----------------
__global__ __launch_bounds__(256) void prep_f(const float* __restrict__ feat)
{
    int bid = blockIdx.x;
    int xg = bid & 3; int cg = (bid >> 2) & 7; int y = (bid >> 5) & 127; int b = bid >> 12;
    __shared__ float ts[32][33];
    int tid = threadIdx.x;
#pragma unroll
    for (int i = 0; i < 4; i++) {
        int f = tid + i*256;
        int cc = f >> 5, xx = f & 31;
        ts[cc][xx] = feat[((size_t)((b*256 + cg*32 + cc)*128 + y) << 7) + xg*32 + xx];
    }
    __syncthreads();
#pragma unroll
    for (int i = 0; i < 2; i++) {
        int f2 = tid + i*256;
        int xx = f2 >> 4;
        int cp = (f2 & 15) * 2;
        float v0 = ts[cp][xx], v1 = ts[cp+1][xx];
        __nv_bfloat16 a1, a2, b1, b2;
        split2(v0, a1, a2); split2(v1, b1, b2);
        size_t o = ((size_t)((b*128 + y)*128 + xg*32 + xx))*256 + cg*32 + cp;
        __nv_bfloat162 p0; p0.x = a1; p0.y = b1;
        __nv_bfloat162 p1; p1.x = a2; p1.y = b2;
        *(__nv_bfloat162*)(g_fs + o)       = p0;
        *(__nv_bfloat162*)(g_fs + FSZ + o) = p1;
    }
}

// ---------------- conv 3x3 + bias + relu via mma.sync bf16x2 + cp.async ----------------
#define ROWB   80
#define A_SPL  (128*ROWB)
#define A_SZ   (2*A_SPL)
#define B_SPL  (64*ROWB)
#define B_SZ   (2*B_SPL)
#define STG_SZ (A_SZ + B_SZ)         // 30720
#define SM_TOTAL (2*STG_SZ)          // 61440

extern __shared__ char cv_smem[];

__global__ __launch_bounds__(256, 2) void conv_tc(const float* __restrict__ bias)
{
    char* smem = cv_smem;
    const uint32_t sbase = smem_u32(smem);
    const int tid  = threadIdx.x;
    const int wid  = tid >> 5;
    const int lane = tid & 31;
    const int wm   = wid & 3;
    const int wn   = wid >> 2;
    const int oc0  = blockIdx.x * 64;
    const int y    = blockIdx.y;
    const int b    = blockIdx.z;

    float acc[2][4][4];
#pragma unroll
    for (int mt = 0; mt < 2; mt++)
#pragma unroll
        for (int nt = 0; nt < 4; nt++)
#pragma unroll
            for (int q = 0; q < 4; q++) acc[mt][nt][q] = 0.f;

    auto issue_stage = [&](int kc) {
        const int st = kc & 1;
        const int tap = kc >> 3, ci0 = (kc & 7) << 5;
        const int ky = tap / 3, kx = tap - ky*3;
        const int yy = y + ky - 1;
        const bool vy = ((unsigned)yy < 128u);
#pragma unroll
        for (int i = 0; i < 6; i++) {
            int v = tid + i*256;
            if (v < 1024) {
                int s = v >> 9;
                int r2 = v & 511;
                int row = r2 >> 2;
                int c   = r2 & 3;
                uint32_t daddr = sbase + st*STG_SZ + s*A_SPL + row*ROWB + c*16;
                int xx = row + kx - 1;
                bool ok = vy && ((unsigned)xx < 128u);
                const __nv_bfloat16* gp = ok
                    ? g_fs + (size_t)s*FSZ + ((size_t)((b*128 + yy)*128 + xx))*256 + ci0 + c*8
                    : g_fs;
                CP_ASYNC16(daddr, gp, ok ? 16 : 0);
            } else {
                int r = v - 1024;
                int s = r >> 8;
                int r2 = r & 255;
                int row = r2 >> 2;
                int c   = r2 & 3;
                uint32_t daddr = sbase + st*STG_SZ + A_SZ + s*B_SPL + row*ROWB + c*16;
                const __nv_bfloat16* gp = g_wb + (size_t)s*WSZ + ((size_t)((oc0 + row)*9 + tap))*256 + ci0 + c*8;
                CP_ASYNC16(daddr, gp, 16);
            }
        }
        CP_COMMIT();
    };

    auto compute = [&](int st) {
        const uint32_t abase = sbase + st*STG_SZ;
        const uint32_t bbase = abase + A_SZ;
#pragma unroll
        for (int h = 0; h < 2; h++) {
            uint32_t colo = h*32 + ((lane >> 4) << 4);
            uint32_t afr[2][2][4];
#pragma unroll
            for (int s = 0; s < 2; s++) {
#pragma unroll
                for (int mt = 0; mt < 2; mt++) {
                    uint32_t addr = abase + s*A_SPL + (wm*32 + mt*16 + (lane & 15))*ROWB + colo;
                    LDMX4(afr[s][mt][0], afr[s][mt][1], afr[s][mt][2], afr[s][mt][3], addr);
                }
            }
#pragma unroll
            for (int sb = 0; sb < 2; sb++) {
                uint32_t bfr[4][2];
#pragma unroll
                for (int p = 0; p < 2; p++) {
                    uint32_t r0, r1, r2, r3;
                    uint32_t addr = bbase + sb*B_SPL + (wn*32 + p*16 + (lane & 15))*ROWB + colo;
                    LDMX4(r0, r1, r2, r3, addr);
                    bfr[2*p][0] = r0;   bfr[2*p][1] = r2;
                    bfr[2*p+1][0] = r1; bfr[2*p+1][1] = r3;
                }
                int nA = (sb == 0) ? 2 : 1;
#pragma unroll
                for (int sa = 0; sa < 2; sa++) {
                    if (sa >= nA) break;
#pragma unroll
                    for (int mt = 0; mt < 2; mt++)
#pragma unroll
                        for (int nt = 0; nt < 4; nt++)
                            MMA16816(acc[mt][nt], afr[sa][mt], bfr[nt]);
                }
            }
        }
    };

    const int NCH = 72;
    issue_stage(0);
#pragma unroll 1
    for (int c = 0; c < NCH; c++) {
        CP_WAIT0();
        __syncthreads();
        if (c + 1 < NCH) issue_stage(c + 1);
        compute(c & 1);
    }

    // epilogue: bias + relu -> bf16x2 split planes (consumed by heads_mma)
    const int gid = lane >> 2, tg = lane & 3;
#pragma unroll
    for (int mt = 0; mt < 2; mt++) {
#pragma unroll
        for (int nt = 0; nt < 4; nt++) {
            int col = oc0 + wn*32 + nt*8 + tg*2;
            float b0 = __ldg(&bias[col]);
            float b1 = __ldg(&bias[col + 1]);
#pragma unroll
            for (int hf = 0; hf < 2; hf++) {
                float vx = fmaxf(acc[mt][nt][hf*2+0] + b0, 0.f);
                float vy = fmaxf(acc[mt][nt][hf*2+1] + b1, 0.f);
                __nv_bfloat16 x1, x2, y1, y2;
                split2(vx, x1, x2); split2(vy, y1, y2);
                size_t base = ((size_t)((b*128 + y)*128 + wm*32 + mt*16 + gid + hf*8))*256 + col;
                __nv_bfloat162 p0; p0.x = x1; p0.y = y1;
                __nv_bfloat162 p1; p1.x = x2; p1.y = y2;
                *(__nv_bfloat162*)(g_ts + base)       = p0;
                *(__nv_bfloat162*)(g_ts + FSZ + base) = p1;
            }
        }
    }
}

// ---------------- heads via mma.sync bf16x2 (M=65536, N=48, K=256) ----------------
// K-chunk 32 (8 chunks); 2 CTAs/SM; histogram fused into epilogue.
#define HA_ROWB 80
#define HA_SPL  (128*HA_ROWB)        // 10240
#define HA_STG  (2*HA_SPL)           // 20480 per stage (2 splits)
#define HB_ROWB 528
#define HB_SPL  (48*HB_ROWB)         // 25344
#define HB_OFF  (2*HA_STG)           // 40960
#define H_TOTAL (HB_OFF + 2*HB_SPL)  // 91648

__global__ __launch_bounds__(256, 2) void heads_mma()
{
    char* smem = cv_smem;
    const uint32_t sbase = smem_u32(smem);
    const int tid  = threadIdx.x;
    const int wm   = tid >> 5;
    const int lane = tid & 31;
    const int px0  = blockIdx.x * 128;

    float acc[6][4];
#pragma unroll
    for (int nt = 0; nt < 6; nt++)
#pragma unroll
        for (int q = 0; q < 4; q++) acc[nt][q] = 0.f;

    // load B (head weights, both splits): 3072 x 16B
#pragma unroll
    for (int i = 0; i < 12; i++) {
        int v = tid + i*256;
        int s = v >= 1536; int r = s ? v - 1536 : v;
        int row = r >> 5, c = r & 31;
        uint32_t daddr = sbase + HB_OFF + s*HB_SPL + row*HB_ROWB + c*16;
        const __nv_bfloat16* gp = g_hwb + (size_t)s*48*256 + row*256 + c*8;
        CP_ASYNC16(daddr, gp, 16);
    }
    CP_COMMIT();

    // A stage: 2 splits x 128 rows x 64B = 1024 x 16B -> 4 per thread
    auto issue_a = [&](int kc) {
        const int st = kc & 1;
#pragma unroll
        for (int i = 0; i < 4; i++) {
            int v = tid + i*256;              // 0..1023
            int s = v >= 512; int r = v & 511;
            int row = r >> 2, c = r & 3;
            uint32_t daddr = sbase + st*HA_STG + s*HA_SPL + row*HA_ROWB + c*16;
            const __nv_bfloat16* gp = g_ts + (size_t)s*FSZ + ((size_t)(px0 + row))*256 + kc*32 + c*8;
            CP_ASYNC16(daddr, gp, 16);
        }
        CP_COMMIT();
    };

    issue_a(0);
#pragma unroll 1
    for (int kc = 0; kc < 8; kc++) {
        CP_WAIT0();
        __syncthreads();
        if (kc + 1 < 8) issue_a(kc + 1);
        const int st = kc & 1;
#pragma unroll
        for (int h = 0; h < 2; h++) {
            uint32_t colo = h*32 + ((lane >> 4) << 4);
            uint32_t afr[2][4];
#pragma unroll
            for (int s = 0; s < 2; s++) {
                uint32_t addr = sbase + st*HA_STG + s*HA_SPL + (wm*16 + (lane & 15))*HA_ROWB + colo;
                LDMX4(afr[s][0], afr[s][1], afr[s][2], afr[s][3], addr);
            }
            uint32_t bcol = kc*64 + h*32 + ((lane >> 4) << 4);
            uint32_t bfr[2][6][2];
#pragma unroll
            for (int s = 0; s < 2; s++) {
#pragma unroll
                for (int p = 0; p < 3; p++) {
                    uint32_t r0, r1, r2, r3;
                    uint32_t addr = sbase + HB_OFF + s*HB_SPL + (p*16 + (lane & 15))*HB_ROWB + bcol;
                    LDMX4(r0, r1, r2, r3, addr);
                    bfr[s][2*p][0] = r0;   bfr[s][2*p][1] = r2;
                    bfr[s][2*p+1][0] = r1; bfr[s][2*p+1][1] = r3;
                }
            }
#pragma unroll
            for (int nt = 0; nt < 6; nt++) {
                MMA16816(acc[nt], afr[0], bfr[0][nt]);
                MMA16816(acc[nt], afr[0], bfr[1][nt]);
                MMA16816(acc[nt], afr[1], bfr[0][nt]);
            }
        }
        __syncthreads();
    }

    // epilogue: bias, scatter to scores/deltas; fused score histogram
    const int gid = lane >> 2, tg = lane & 3;
#pragma unroll
    for (int nt = 0; nt < 6; nt++) {
#pragma unroll
        for (int hf = 0; hf < 2; hf++) {
            int px = px0 + wm*16 + gid + hf*8;
            int b  = px >> 14;
            int pxi = px & 16383;
#pragma unroll
            for (int e = 0; e < 2; e++) {
                int o = nt*8 + tg*2 + e;
                float v = acc[nt][hf*2 + e] + g_hb[o];
                if (o < 9) {
                    g_scores[(size_t)b*NSC + pxi*9 + o] = v;
                    atomicAdd(&g_h16[b*65536 + (okey(v) >> 16)], 1u);
                } else if (o < 45) {
                    int q = o - 9;
                    g_deltas[((size_t)b*NSC + pxi*9 + (q >> 2))*4 + (q & 3)] = v;
                }
            }
        }
    }
}

// ---------------- select ----------------
__global__ __launch_bounds__(1024) void sel_scan()
{
    const int b = blockIdx.x;
    const int tid = threadIdx.x;
    __shared__ unsigned part[1024];
    if (tid == 0) { g_cG[b] = 0u; g_cE[b] = 0u; }
    unsigned local = 0;
    const unsigned* hb = g_h16 + b*65536 + tid*64;
#pragma unroll 8
    for (int j = 0; j < 64; j++) local += hb[j];
    part[tid] = local;
    __syncthreads();
    if (tid == 0) {
        unsigned cum = 0; int tt = 1023;
        for (; tt >= 0; tt--) {
            if (cum + part[tt] >= PRE_K) break;
            cum += part[tt];
        }
        const unsigned* hbb = g_h16 + b*65536 + tt*64;
        unsigned c2 = cum; int binT = tt*64;
        for (int j = 63; j >= 0; j--) {
            unsigned h = hbb[j];
            if (c2 + h >= PRE_K) { binT = tt*64 + j; break; }
            c2 += h;
        }
        g_T16[b] = (unsigned)binT;
    }
}

__global__ __launch_bounds__(512) void sel_collect()
{
    const int b = blockIdx.y;
    const unsigned T = g_T16[b];
    const float4* sc4 = (const float4*)(g_scores + (size_t)b*NSC);
    int idx = blockIdx.x*512 + threadIdx.x;
    float4 v = sc4[idx];
    float va[4] = {v.x, v.y, v.z, v.w};
#pragma unroll
    for (int e = 0; e < 4; e++) {
        unsigned n = (unsigned)(idx*4 + e);
        unsigned k = okey(va[e]);
        unsigned hi = k >> 16;
        unsigned long long pk = (((unsigned long long)k) << 32) | (unsigned long long)(0xFFFFFFFFu - n);
        if (hi > T) {
            unsigned pos = atomicAdd(&g_cG[b], 1u);
            if (pos < 1024u) g_candG[b*1024 + pos] = pk;
        } else if (hi == T) {
            unsigned pos = atomicAdd(&g_cE[b], 1u);
            if (pos < 1024u) g_candE[b*1024 + pos] = pk;
        }
    }
    // self-clean the histogram for the next graph replay
    int lin = (b*72 + blockIdx.x)*512 + threadIdx.x;
#pragma unroll
    for (int z = 0; z < 2; z++) {
        int w = lin*2 + z;
        if (w < BATCH*65536) g_h16[w] = 0u;
    }
}

// sort + decode + clip (merged)
__global__ __launch_bounds__(1024) void sel_final(const int* ihp, const int* iwp)
{
    const int b = blockIdx.x;
    const int tid = threadIdx.x;
    __shared__ unsigned long long val[2048];
    unsigned nG = g_cG[b]; if (nG > 1024u) nG = 1024u;
    unsigned nE = g_cE[b]; if (nE > 1024u) nE = 1024u;
    val[tid]        = (tid < (int)nG) ? g_candG[b*1024 + tid] : 0ull;
    val[1024 + tid] = (tid < (int)nE) ? g_candE[b*1024 + tid] : 0ull;
    __syncthreads();
    for (int k = 2; k <= 2048; k <<= 1) {
        for (int j = k >> 1; j > 0; j >>= 1) {
#pragma unroll
            for (int e = 0; e < 2; e++) {
                int i = tid + e*1024;
                int ixj = i ^ j;
                if (ixj > i) {
                    unsigned long long a = val[i], c = val[ixj];
                    bool descBlock = ((i & k) == 0);
                    if ((a < c) == descBlock) { val[i] = c; val[ixj] = a; }
                }
            }
            __syncthreads();
        }
    }
    if (tid >= PRE_K) return;
    const float img_h = dimval(ihp);
    const float img_w = dimval(iwp);
    unsigned n = 0xFFFFFFFFu - (unsigned)(val[tid] & 0xFFFFFFFFull);
    int a  = n % 9;
    int px = n / 9;
    int x  = px & 127, y = px >> 7;
    float sx = x * 16.0f, sy = y * 16.0f;

    float b0 = g_anch[a*4+0], b1 = g_anch[a*4+1], b2 = g_anch[a*4+2], b3 = g_anch[a*4+3];
    float ax1 = b0 + sx, ay1 = b1 + sy, ax2 = b2 + sx, ay2 = b3 + sy;
    float w = ax2 - ax1, h = ay2 - ay1;
    float cx = ax1 + 0.5f*w, cy = ay1 + 0.5f*h;

    const float* d = &g_deltas[((size_t)b*NSC + n)*4];
    float dx = d[0], dy = d[1], dw = d[2], dh = d[3];
    float pcx = cx + dx*w, pcy = cy + dy*h;
    float pw = w * expf(dw), ph = h * expf(dh);
    float x1 = pcx - 0.5f*pw, y1 = pcy - 0.5f*ph;
    float x2 = pcx + 0.5f*pw, y2 = pcy + 0.5f*ph;
    x1 = fminf(fmaxf(x1, 0.f), img_w);
    y1 = fminf(fmaxf(y1, 0.f), img_h);
    x2 = fminf(fmaxf(x2, 0.f), img_w);
    y2 = fminf(fmaxf(y2, 0.f), img_h);

    float* ob = &g_boxes[(b*PRE_K + tid)*4];
    ob[0] = x1; ob[1] = y1; ob[2] = x2; ob[3] = y2;
}

// ---------------- NMS suppression bitmask ----------------
__global__ void nms_mask_kernel()
{
    const int b = blockIdx.z, cbk = blockIdx.x, rbk = blockIdx.y, t = threadIdx.x;
    __shared__ float4 colb[32];
    int j = cbk*32 + t;
    if (j < PRE_K) colb[t] = *(const float4*)&g_boxes[(b*PRE_K + j)*4];
    __syncthreads();

    int i = rbk*32 + t;
    if (i >= PRE_K) return;
    float4 bi = *(const float4*)&g_boxes[(b*PRE_K + i)*4];
    float ai = (bi.z - bi.x) * (bi.w - bi.y);
    unsigned bits = 0u;
#pragma unroll
    for (int jj = 0; jj < 32; jj++) {
        int jg = cbk*32 + jj;
        if (jg >= PRE_K) break;
        if (jg <= i) continue;
        float4 bj = colb[jj];
        float xx1 = fmaxf(bi.x, bj.x), yy1 = fmaxf(bi.y, bj.y);
        float xx2 = fminf(bi.z, bj.z), yy2 = fminf(bi.w, bj.w);
        float inter = fmaxf(xx2 - xx1, 0.f) * fmaxf(yy2 - yy1, 0.f);
        float aj = (bj.z - bj.x) * (bj.w - bj.y);
        float iou = inter / (ai + aj - inter);
        if (iou > NMS_T) bits |= (1u << jj);
    }
    g_mask[(b*PRE_K + i)*MASKW + cbk] = bits;
}

// ---------------- sequential greedy scan + emit ----------------
__global__ void final_kernel(float* __restrict__ out)
{
    const int b = blockIdx.x;
    if (threadIdx.x != 0) return;
    unsigned remv[MASKW];
#pragma unroll
    for (int w = 0; w < MASKW; w++) remv[w] = 0u;
    int nk = 0;
    for (int i = 0; i < PRE_K; i++) {
        if (!((remv[i >> 5] >> (i & 31)) & 1u)) {
            const float* bx = &g_boxes[(b*PRE_K + i)*4];
            float* o = &out[(b*POST_K + nk)*4];
            o[0] = bx[0]; o[1] = bx[1]; o[2] = bx[2]; o[3] = bx[3];
            nk++;
            if (nk >= POST_K) break;
            const unsigned* m = &g_mask[(b*PRE_K + i)*MASKW];
#pragma unroll
            for (int w = 0; w < MASKW; w++) remv[w] |= m[w];
        }
    }
    for (int k = nk; k < POST_K; k++) {
        float* o = &out[(b*POST_K + k)*4];
        o[0] = 0.f; o[1] = 0.f; o[2] = 0.f; o[3] = 0.f;
    }
}

// ---------------- launcher ----------------
extern "C" void kernel_launch(void* const* d_in, const int* in_sizes, int n_in,
                              void* d_out, int out_size)
{
    const float* feat = (const float*)d_in[0];
    const float* cw   = (const float*)d_in[1];
    const float* cb   = (const float*)d_in[2];
    const float* clw  = (const float*)d_in[3];
    const float* clb  = (const float*)d_in[4];
    const float* bw   = (const float*)d_in[5];
    const float* bb   = (const float*)d_in[6];
    const int*   ihp  = (const int*)d_in[7];
    const int*   iwp  = (const int*)d_in[8];
    float* out = (float*)d_out;

    static int smem_set = 0;
    if (!smem_set) {
        cudaFuncSetAttribute(conv_tc,   cudaFuncAttributeMaxDynamicSharedMemorySize, SM_TOTAL);
        cudaFuncSetAttribute(heads_mma, cudaFuncAttributeMaxDynamicSharedMemorySize, H_TOTAL);
        smem_set = 1;
    }

    prep_wh<<<2353, 256>>>(cw, clw, clb, bw, bb);
    prep_f<<<16384, 256>>>(feat);
    conv_tc<<<dim3(4, 128, 4), 256, SM_TOTAL>>>(cb);
    heads_mma<<<512, 256, H_TOTAL>>>();
    sel_scan<<<BATCH, 1024>>>();
    sel_collect<<<dim3(72, BATCH), 512>>>();
    sel_final<<<BATCH, 1024>>>(ihp, iwp);
    nms_mask_kernel<<<dim3(MASKW, MASKW, BATCH), 32>>>();
    final_kernel<<<BATCH, 32>>>(out);
}

// round 16
// speedup vs baseline: 1.0012x; 1.0012x over previous
#include <cuda_runtime.h>
#include <cuda_bf16.h>
#include <cstdint>
#include <math.h>

// ---------------- problem constants ----------------
#define BATCH 4
#define CIN   256
#define HH    128
#define WW    128
#define NANCH 9
#define NPIX  (HH*WW)         // 16384
#define NSC   (NPIX*NANCH)    // 147456 per image
#define PRE_K 600
#define POST_K 100
#define NMS_T 0.7f
#define MASKW 19              // ceil(600/32)

#define FSZ ((size_t)BATCH*NPIX*CIN)     // 16777216 elems per split
#define WSZ ((size_t)256*9*256)          // 589824 elems per split

// ---------------- device scratch (static; no allocations) ----------------
__device__ __align__(16) __nv_bfloat16 g_fs[2*FSZ];               // features NHWC, bf16 x2 splits
__device__ __align__(16) __nv_bfloat16 g_ts[2*FSZ];               // conv out NHWC, bf16 x2 splits
__device__ __align__(16) __nv_bfloat16 g_wb[2*WSZ];               // conv weights [s][oc][tap][ci]
__device__ __align__(16) __nv_bfloat16 g_hwb[2*48*256];           // head weights [s][o][k] bf16
__device__ float g_hb[48];
__device__ __align__(16) float g_anch[NANCH*4];
__device__ __align__(16) float g_scores[BATCH*NSC];
__device__ __align__(16) float g_deltas[(size_t)BATCH*NSC*4];
__device__ unsigned g_h16[BATCH*65536];
__device__ unsigned g_cG[BATCH], g_cE[BATCH], g_T16[BATCH];
__device__ __align__(16) unsigned long long g_candG[BATCH*1024];
__device__ __align__(16) unsigned long long g_candE[BATCH*1024];
__device__ __align__(16) float g_boxes[BATCH*PRE_K*4];
__device__ unsigned g_mask[BATCH*PRE_K*MASKW];

// ---------------- small helpers ----------------
__device__ __forceinline__ unsigned okey(float f) {
    unsigned u = __float_as_uint(f);
    return (u & 0x80000000u) ? ~u : (u | 0x80000000u);
}
__device__ __forceinline__ float dimval(const int* p) {
    int raw = *p;
    if (raw > 0 && raw < 1000000) return (float)raw;
    return __int_as_float(raw);
}
__device__ __forceinline__ uint32_t smem_u32(const void* p) {
    uint32_t a;
    asm("{ .reg .u64 t; cvta.to.shared.u64 t, %1; cvt.u32.u64 %0, t; }" : "=r"(a) : "l"(p));
    return a;
}
__device__ __forceinline__ void split2(float v, __nv_bfloat16& h1, __nv_bfloat16& h2) {
    h1 = __float2bfloat16_rn(v);
    h2 = __float2bfloat16_rn(v - __bfloat162float(h1));
}

#define LDMX4(r0,r1,r2,r3,addr) \
    asm volatile("ldmatrix.sync.aligned.m8n8.x4.shared.b16 {%0,%1,%2,%3}, [%4];" \
        : "=r"(r0), "=r"(r1), "=r"(r2), "=r"(r3) : "r"(addr))

#define MMA16816(d,a,b) \
    asm volatile("mma.sync.aligned.m16n8k16.row.col.f32.bf16.bf16.f32 " \
        "{%0,%1,%2,%3}, {%4,%5,%6,%7}, {%8,%9}, {%0,%1,%2,%3};" \
        : "+f"((d)[0]), "+f"((d)[1]), "+f"((d)[2]), "+f"((d)[3]) \
        : "r"((a)[0]), "r"((a)[1]), "r"((a)[2]), "r"((a)[3]), "r"((b)[0]), "r"((b)[1]))

#define CP_ASYNC16(daddr, gptr, sz) \
    asm volatile("cp.async.cg.shared.global [%0], [%1], 16, %2;" \
        :: "r"(daddr), "l"(gptr), "r"(sz))
#define CP_COMMIT() asm volatile("cp.async.commit_group;" ::: "memory")
#define CP_WAIT0()  asm volatile("cp.async.wait_group 0;" ::: "memory")

// ---------------- prep: conv weights + head weights + bias + anchors ----------------
__global__ void prep_wh(const float* __restrict__ cw,
                        const float* __restrict__ clw, const float* __restrict__ clb,
                        const float* __restrict__ bw,  const float* __restrict__ bb)
{
    int i = blockIdx.x * 256 + threadIdx.x;
    if (i < (int)WSZ) {
        int oc = i / 2304; int r = i - oc*2304; int tap = r >> 8; int ci = r & 255;
        float v = cw[(oc*256 + ci)*9 + tap];
        __nv_bfloat16 h1, h2; split2(v, h1, h2);
        g_wb[i] = h1; g_wb[WSZ + i] = h2;
        return;
    }
    i -= (int)WSZ;
    if (i < 48*256) {
        int o = i >> 8; int k = i & 255;
        float v = 0.f;
        if (o < 9) v = clw[o*256 + k];
        else if (o < 45) v = bw[(o-9)*256 + k];
        __nv_bfloat16 h1, h2; split2(v, h1, h2);
        g_hwb[i] = h1; g_hwb[48*256 + i] = h2;
        return;
    }
    i -= 48*256;
    if (i < 48) {
        float v = 0.f;
        if (i < 9) v = clb[i]; else if (i < 45) v = bb[i-9];
        g_hb[i] = v;
        return;
    }
    i -= 48;
    if (i < 36) {
        int a = i >> 2, c = i & 3;
        int si = a / 3, ri = a - si*3;
        double sc = (si == 0) ? 8.0 : (si == 1) ? 16.0 : 32.0;
        double rt = (ri == 0) ? 0.5 : (ri == 1) ? 1.0 : 2.0;
        double w = 16.0 * sc * sqrt(rt);
        double h = 16.0 * sc / sqrt(rt);
        double v = (c == 0) ? (-w*0.5) : (c == 1) ? (-h*0.5) : (c == 2) ? (w*0.5) : (h*0.5);
        g_anch[i] = (float)v;
    }
}

// ---------------- prep: feature NCHW fp32 -> NHWC bf16 x2 (vectorized stores) ----------------
__global__ __launch_bounds__(256) void prep_f(const float* __restrict__ feat)
{
    int bid = blockIdx.x;
    int xg = bid & 3; int cg = (bid >> 2) & 7; int y = (bid >> 5) & 127; int b = bid >> 12;
    __shared__ float ts[32][33];
    int tid = threadIdx.x;
#pragma unroll
    for (int i = 0; i < 4; i++) {
        int f = tid + i*256;
        int cc = f >> 5, xx = f & 31;
        ts[cc][xx] = feat[((size_t)((b*256 + cg*32 + cc)*128 + y) << 7) + xg*32 + xx];
    }
    __syncthreads();
#pragma unroll
    for (int i = 0; i < 2; i++) {
        int f2 = tid + i*256;
        int xx = f2 >> 4;
        int cp = (f2 & 15) * 2;
        float v0 = ts[cp][xx], v1 = ts[cp+1][xx];
        __nv_bfloat16 a1, a2, b1, b2;
        split2(v0, a1, a2); split2(v1, b1, b2);
        size_t o = ((size_t)((b*128 + y)*128 + xg*32 + xx))*256 + cg*32 + cp;
        __nv_bfloat162 p0; p0.x = a1; p0.y = b1;
        __nv_bfloat162 p1; p1.x = a2; p1.y = b2;
        *(__nv_bfloat162*)(g_fs + o)       = p0;
        *(__nv_bfloat162*)(g_fs + FSZ + o) = p1;
    }
}

// ---------------- conv 3x3 + bias + relu via mma.sync bf16x2 + cp.async ----------------
#define ROWB   80
#define A_SPL  (128*ROWB)
#define A_SZ   (2*A_SPL)
#define B_SPL  (64*ROWB)
#define B_SZ   (2*B_SPL)
#define STG_SZ (A_SZ + B_SZ)         // 30720
#define SM_TOTAL (2*STG_SZ)          // 61440

extern __shared__ char cv_smem[];

__global__ __launch_bounds__(256, 2) void conv_tc(const float* __restrict__ bias)
{
    char* smem = cv_smem;
    const uint32_t sbase = smem_u32(smem);
    const int tid  = threadIdx.x;
    const int wid  = tid >> 5;
    const int lane = tid & 31;
    const int wm   = wid & 3;
    const int wn   = wid >> 2;
    const int oc0  = blockIdx.x * 64;
    const int y    = blockIdx.y;
    const int b    = blockIdx.z;

    float acc[2][4][4];
#pragma unroll
    for (int mt = 0; mt < 2; mt++)
#pragma unroll
        for (int nt = 0; nt < 4; nt++)
#pragma unroll
            for (int q = 0; q < 4; q++) acc[mt][nt][q] = 0.f;

    auto issue_stage = [&](int kc) {
        const int st = kc & 1;
        const int tap = kc >> 3, ci0 = (kc & 7) << 5;
        const int ky = tap / 3, kx = tap - ky*3;
        const int yy = y + ky - 1;
        const bool vy = ((unsigned)yy < 128u);
#pragma unroll
        for (int i = 0; i < 6; i++) {
            int v = tid + i*256;
            if (v < 1024) {
                int s = v >> 9;
                int r2 = v & 511;
                int row = r2 >> 2;
                int c   = r2 & 3;
                uint32_t daddr = sbase + st*STG_SZ + s*A_SPL + row*ROWB + c*16;
                int xx = row + kx - 1;
                bool ok = vy && ((unsigned)xx < 128u);
                const __nv_bfloat16* gp = ok
                    ? g_fs + (size_t)s*FSZ + ((size_t)((b*128 + yy)*128 + xx))*256 + ci0 + c*8
                    : g_fs;
                CP_ASYNC16(daddr, gp, ok ? 16 : 0);
            } else {
                int r = v - 1024;
                int s = r >> 8;
                int r2 = r & 255;
                int row = r2 >> 2;
                int c   = r2 & 3;
                uint32_t daddr = sbase + st*STG_SZ + A_SZ + s*B_SPL + row*ROWB + c*16;
                const __nv_bfloat16* gp = g_wb + (size_t)s*WSZ + ((size_t)((oc0 + row)*9 + tap))*256 + ci0 + c*8;
                CP_ASYNC16(daddr, gp, 16);
            }
        }
        CP_COMMIT();
    };

    auto compute = [&](int st) {
        const uint32_t abase = sbase + st*STG_SZ;
        const uint32_t bbase = abase + A_SZ;
#pragma unroll
        for (int h = 0; h < 2; h++) {
            uint32_t colo = h*32 + ((lane >> 4) << 4);
            uint32_t afr[2][2][4];
#pragma unroll
            for (int s = 0; s < 2; s++) {
#pragma unroll
                for (int mt = 0; mt < 2; mt++) {
                    uint32_t addr = abase + s*A_SPL + (wm*32 + mt*16 + (lane & 15))*ROWB + colo;
                    LDMX4(afr[s][mt][0], afr[s][mt][1], afr[s][mt][2], afr[s][mt][3], addr);
                }
            }
#pragma unroll
            for (int sb = 0; sb < 2; sb++) {
                uint32_t bfr[4][2];
#pragma unroll
                for (int p = 0; p < 2; p++) {
                    uint32_t r0, r1, r2, r3;
                    uint32_t addr = bbase + sb*B_SPL + (wn*32 + p*16 + (lane & 15))*ROWB + colo;
                    LDMX4(r0, r1, r2, r3, addr);
                    bfr[2*p][0] = r0;   bfr[2*p][1] = r2;
                    bfr[2*p+1][0] = r1; bfr[2*p+1][1] = r3;
                }
                int nA = (sb == 0) ? 2 : 1;
#pragma unroll
                for (int sa = 0; sa < 2; sa++) {
                    if (sa >= nA) break;
#pragma unroll
                    for (int mt = 0; mt < 2; mt++)
#pragma unroll
                        for (int nt = 0; nt < 4; nt++)
                            MMA16816(acc[mt][nt], afr[sa][mt], bfr[nt]);
                }
            }
        }
    };

    const int NCH = 72;
    issue_stage(0);
#pragma unroll 1
    for (int c = 0; c < NCH; c++) {
        CP_WAIT0();
        __syncthreads();
        if (c + 1 < NCH) issue_stage(c + 1);
        compute(c & 1);
    }

    // epilogue: bias + relu -> bf16x2 split planes (consumed by heads_mma)
    const int gid = lane >> 2, tg = lane & 3;
#pragma unroll
    for (int mt = 0; mt < 2; mt++) {
#pragma unroll
        for (int nt = 0; nt < 4; nt++) {
            int col = oc0 + wn*32 + nt*8 + tg*2;
            float b0 = __ldg(&bias[col]);
            float b1 = __ldg(&bias[col + 1]);
#pragma unroll
            for (int hf = 0; hf < 2; hf++) {
                float vx = fmaxf(acc[mt][nt][hf*2+0] + b0, 0.f);
                float vy = fmaxf(acc[mt][nt][hf*2+1] + b1, 0.f);
                __nv_bfloat16 x1, x2, y1, y2;
                split2(vx, x1, x2); split2(vy, y1, y2);
                size_t base = ((size_t)((b*128 + y)*128 + wm*32 + mt*16 + gid + hf*8))*256 + col;
                __nv_bfloat162 p0; p0.x = x1; p0.y = y1;
                __nv_bfloat162 p1; p1.x = x2; p1.y = y2;
                *(__nv_bfloat162*)(g_ts + base)       = p0;
                *(__nv_bfloat162*)(g_ts + FSZ + base) = p1;
            }
        }
    }
}

// ---------------- heads via mma.sync bf16x2 (M=65536, N=48, K=256) ----------------
// K-chunk 64 (4 chunks); B sliced per-chunk into the stage -> 2 CTAs/SM.
#define HA_ROWB 144
#define HA_SPL  (128*HA_ROWB)        // 18432 per split
#define HA_SZ   (2*HA_SPL)           // 36864
#define HBS_ROWB 144
#define HBS_SPL (48*HBS_ROWB)        // 6912 per split
#define HBS_SZ  (2*HBS_SPL)          // 13824
#define HSTG    (HA_SZ + HBS_SZ)     // 50688
#define H_TOTAL (2*HSTG)             // 101376

__global__ __launch_bounds__(256, 2) void heads_mma()
{
    char* smem = cv_smem;
    const uint32_t sbase = smem_u32(smem);
    const int tid  = threadIdx.x;
    const int wm   = tid >> 5;
    const int lane = tid & 31;
    const int px0  = blockIdx.x * 128;

    float acc[6][4];
#pragma unroll
    for (int nt = 0; nt < 6; nt++)
#pragma unroll
        for (int q = 0; q < 4; q++) acc[nt][q] = 0.f;

    // stage = A (2 splits x 128 rows x 128B) + B slice (2 splits x 48 rows x 128B)
    // copies: A 2048 + B 768 = 2816 -> 11 per thread
    auto issue_stage = [&](int kc) {
        const int st = kc & 1;
#pragma unroll
        for (int i = 0; i < 11; i++) {
            int v = tid + i*256;              // 0..2815
            if (v < 2048) {
                int s = v >> 10; int r = v & 1023;
                int row = r >> 3, c = r & 7;
                uint32_t daddr = sbase + st*HSTG + s*HA_SPL + row*HA_ROWB + c*16;
                const __nv_bfloat16* gp = g_ts + (size_t)s*FSZ + ((size_t)(px0 + row))*256 + kc*64 + c*8;
                CP_ASYNC16(daddr, gp, 16);
            } else {
                int r = v - 2048;             // 0..767
                int s = r >= 384; int r2 = s ? r - 384 : r;
                int row = r2 >> 3, c = r2 & 7;
                uint32_t daddr = sbase + st*HSTG + HA_SZ + s*HBS_SPL + row*HBS_ROWB + c*16;
                const __nv_bfloat16* gp = g_hwb + (size_t)s*48*256 + row*256 + kc*64 + c*8;
                CP_ASYNC16(daddr, gp, 16);
            }
        }
        CP_COMMIT();
    };

    issue_stage(0);
#pragma unroll 1
    for (int kc = 0; kc < 4; kc++) {
        CP_WAIT0();
        __syncthreads();
        if (kc + 1 < 4) issue_stage(kc + 1);
        const int st = kc & 1;
        const uint32_t abase = sbase + st*HSTG;
        const uint32_t bbase = abase + HA_SZ;
#pragma unroll
        for (int h = 0; h < 4; h++) {
            uint32_t colo = h*32 + ((lane >> 4) << 4);
            uint32_t afr[2][4];
#pragma unroll
            for (int s = 0; s < 2; s++) {
                uint32_t addr = abase + s*HA_SPL + (wm*16 + (lane & 15))*HA_ROWB + colo;
                LDMX4(afr[s][0], afr[s][1], afr[s][2], afr[s][3], addr);
            }
            uint32_t bfr[2][6][2];
#pragma unroll
            for (int s = 0; s < 2; s++) {
#pragma unroll
                for (int p = 0; p < 3; p++) {
                    uint32_t r0, r1, r2, r3;
                    uint32_t addr = bbase + s*HBS_SPL + (p*16 + (lane & 15))*HBS_ROWB + colo;
                    LDMX4(r0, r1, r2, r3, addr);
                    bfr[s][2*p][0] = r0;   bfr[s][2*p][1] = r2;
                    bfr[s][2*p+1][0] = r1; bfr[s][2*p+1][1] = r3;
                }
            }
#pragma unroll
            for (int nt = 0; nt < 6; nt++) {
                MMA16816(acc[nt], afr[0], bfr[0][nt]);
                MMA16816(acc[nt], afr[0], bfr[1][nt]);
                MMA16816(acc[nt], afr[1], bfr[0][nt]);
            }
        }
    }

    // epilogue: bias, scatter to scores/deltas; fused score histogram
    const int gid = lane >> 2, tg = lane & 3;
#pragma unroll
    for (int nt = 0; nt < 6; nt++) {
#pragma unroll
        for (int hf = 0; hf < 2; hf++) {
            int px = px0 + wm*16 + gid + hf*8;
            int b  = px >> 14;
            int pxi = px & 16383;
#pragma unroll
            for (int e = 0; e < 2; e++) {
                int o = nt*8 + tg*2 + e;
                float v = acc[nt][hf*2 + e] + g_hb[o];
                if (o < 9) {
                    g_scores[(size_t)b*NSC + pxi*9 + o] = v;
                    atomicAdd(&g_h16[b*65536 + (okey(v) >> 16)], 1u);
                } else if (o < 45) {
                    int q = o - 9;
                    g_deltas[((size_t)b*NSC + pxi*9 + (q >> 2))*4 + (q & 3)] = v;
                }
            }
        }
    }
}

// ---------------- select ----------------
__global__ __launch_bounds__(1024) void sel_scan()
{
    const int b = blockIdx.x;
    const int tid = threadIdx.x;
    __shared__ unsigned part[1024];
    if (tid == 0) { g_cG[b] = 0u; g_cE[b] = 0u; }
    unsigned local = 0;
    const unsigned* hb = g_h16 + b*65536 + tid*64;
#pragma unroll 8
    for (int j = 0; j < 64; j++) local += hb[j];
    part[tid] = local;
    __syncthreads();
    if (tid == 0) {
        unsigned cum = 0; int tt = 1023;
        for (; tt >= 0; tt--) {
            if (cum + part[tt] >= PRE_K) break;
            cum += part[tt];
        }
        const unsigned* hbb = g_h16 + b*65536 + tt*64;
        unsigned c2 = cum; int binT = tt*64;
        for (int j = 63; j >= 0; j--) {
            unsigned h = hbb[j];
            if (c2 + h >= PRE_K) { binT = tt*64 + j; break; }
            c2 += h;
        }
        g_T16[b] = (unsigned)binT;
    }
}

__global__ __launch_bounds__(512) void sel_collect()
{
    const int b = blockIdx.y;
    const unsigned T = g_T16[b];
    const float4* sc4 = (const float4*)(g_scores + (size_t)b*NSC);
    int idx = blockIdx.x*512 + threadIdx.x;
    float4 v = sc4[idx];
    float va[4] = {v.x, v.y, v.z, v.w};
#pragma unroll
    for (int e = 0; e < 4; e++) {
        unsigned n = (unsigned)(idx*4 + e);
        unsigned k = okey(va[e]);
        unsigned hi = k >> 16;
        unsigned long long pk = (((unsigned long long)k) << 32) | (unsigned long long)(0xFFFFFFFFu - n);
        if (hi > T) {
            unsigned pos = atomicAdd(&g_cG[b], 1u);
            if (pos < 1024u) g_candG[b*1024 + pos] = pk;
        } else if (hi == T) {
            unsigned pos = atomicAdd(&g_cE[b], 1u);
            if (pos < 1024u) g_candE[b*1024 + pos] = pk;
        }
    }
    // self-clean the histogram for the next graph replay
    int lin = (b*72 + blockIdx.x)*512 + threadIdx.x;
#pragma unroll
    for (int z = 0; z < 2; z++) {
        int w = lin*2 + z;
        if (w < BATCH*65536) g_h16[w] = 0u;
    }
}

// sort + decode + clip (merged)
__global__ __launch_bounds__(1024) void sel_final(const int* ihp, const int* iwp)
{
    const int b = blockIdx.x;
    const int tid = threadIdx.x;
    __shared__ unsigned long long val[2048];
    unsigned nG = g_cG[b]; if (nG > 1024u) nG = 1024u;
    unsigned nE = g_cE[b]; if (nE > 1024u) nE = 1024u;
    val[tid]        = (tid < (int)nG) ? g_candG[b*1024 + tid] : 0ull;
    val[1024 + tid] = (tid < (int)nE) ? g_candE[b*1024 + tid] : 0ull;
    __syncthreads();
    for (int k = 2; k <= 2048; k <<= 1) {
        for (int j = k >> 1; j > 0; j >>= 1) {
#pragma unroll
            for (int e = 0; e < 2; e++) {
                int i = tid + e*1024;
                int ixj = i ^ j;
                if (ixj > i) {
                    unsigned long long a = val[i], c = val[ixj];
                    bool descBlock = ((i & k) == 0);
                    if ((a < c) == descBlock) { val[i] = c; val[ixj] = a; }
                }
            }
            __syncthreads();
        }
    }
    if (tid >= PRE_K) return;
    const float img_h = dimval(ihp);
    const float img_w = dimval(iwp);
    unsigned n = 0xFFFFFFFFu - (unsigned)(val[tid] & 0xFFFFFFFFull);
    int a  = n % 9;
    int px = n / 9;
    int x  = px & 127, y = px >> 7;
    float sx = x * 16.0f, sy = y * 16.0f;

    float b0 = g_anch[a*4+0], b1 = g_anch[a*4+1], b2 = g_anch[a*4+2], b3 = g_anch[a*4+3];
    float ax1 = b0 + sx, ay1 = b1 + sy, ax2 = b2 + sx, ay2 = b3 + sy;
    float w = ax2 - ax1, h = ay2 - ay1;
    float cx = ax1 + 0.5f*w, cy = ay1 + 0.5f*h;

    const float* d = &g_deltas[((size_t)b*NSC + n)*4];
    float dx = d[0], dy = d[1], dw = d[2], dh = d[3];
    float pcx = cx + dx*w, pcy = cy + dy*h;
    float pw = w * expf(dw), ph = h * expf(dh);
    float x1 = pcx - 0.5f*pw, y1 = pcy - 0.5f*ph;
    float x2 = pcx + 0.5f*pw, y2 = pcy + 0.5f*ph;
    x1 = fminf(fmaxf(x1, 0.f), img_w);
    y1 = fminf(fmaxf(y1, 0.f), img_h);
    x2 = fminf(fmaxf(x2, 0.f), img_w);
    y2 = fminf(fmaxf(y2, 0.f), img_h);

    float* ob = &g_boxes[(b*PRE_K + tid)*4];
    ob[0] = x1; ob[1] = y1; ob[2] = x2; ob[3] = y2;
}

// ---------------- NMS suppression bitmask ----------------
__global__ void nms_mask_kernel()
{
    const int b = blockIdx.z, cbk = blockIdx.x, rbk = blockIdx.y, t = threadIdx.x;
    __shared__ float4 colb[32];
    int j = cbk*32 + t;
    if (j < PRE_K) colb[t] = *(const float4*)&g_boxes[(b*PRE_K + j)*4];
    __syncthreads();

    int i = rbk*32 + t;
    if (i >= PRE_K) return;
    float4 bi = *(const float4*)&g_boxes[(b*PRE_K + i)*4];
    float ai = (bi.z - bi.x) * (bi.w - bi.y);
    unsigned bits = 0u;
#pragma unroll
    for (int jj = 0; jj < 32; jj++) {
        int jg = cbk*32 + jj;
        if (jg >= PRE_K) break;
        if (jg <= i) continue;
        float4 bj = colb[jj];
        float xx1 = fmaxf(bi.x, bj.x), yy1 = fmaxf(bi.y, bj.y);
        float xx2 = fminf(bi.z, bj.z), yy2 = fminf(bi.w, bj.w);
        float inter = fmaxf(xx2 - xx1, 0.f) * fmaxf(yy2 - yy1, 0.f);
        float aj = (bj.z - bj.x) * (bj.w - bj.y);
        float iou = inter / (ai + aj - inter);
        if (iou > NMS_T) bits |= (1u << jj);
    }
    g_mask[(b*PRE_K + i)*MASKW + cbk] = bits;
}

// ---------------- sequential greedy scan + emit ----------------
__global__ void final_kernel(float* __restrict__ out)
{
    const int b = blockIdx.x;
    if (threadIdx.x != 0) return;
    unsigned remv[MASKW];
#pragma unroll
    for (int w = 0; w < MASKW; w++) remv[w] = 0u;
    int nk = 0;
    for (int i = 0; i < PRE_K; i++) {
        if (!((remv[i >> 5] >> (i & 31)) & 1u)) {
            const float* bx = &g_boxes[(b*PRE_K + i)*4];
            float* o = &out[(b*POST_K + nk)*4];
            o[0] = bx[0]; o[1] = bx[1]; o[2] = bx[2]; o[3] = bx[3];
            nk++;
            if (nk >= POST_K) break;
            const unsigned* m = &g_mask[(b*PRE_K + i)*MASKW];
#pragma unroll
            for (int w = 0; w < MASKW; w++) remv[w] |= m[w];
        }
    }
    for (int k = nk; k < POST_K; k++) {
        float* o = &out[(b*POST_K + k)*4];
        o[0] = 0.f; o[1] = 0.f; o[2] = 0.f; o[3] = 0.f;
    }
}

// ---------------- launcher ----------------
extern "C" void kernel_launch(void* const* d_in, const int* in_sizes, int n_in,
                              void* d_out, int out_size)
{
    const float* feat = (const float*)d_in[0];
    const float* cw   = (const float*)d_in[1];
    const float* cb   = (const float*)d_in[2];
    const float* clw  = (const float*)d_in[3];
    const float* clb  = (const float*)d_in[4];
    const float* bw   = (const float*)d_in[5];
    const float* bb   = (const float*)d_in[6];
    const int*   ihp  = (const int*)d_in[7];
    const int*   iwp  = (const int*)d_in[8];
    float* out = (float*)d_out;

    static int smem_set = 0;
    if (!smem_set) {
        cudaFuncSetAttribute(conv_tc,   cudaFuncAttributeMaxDynamicSharedMemorySize, SM_TOTAL);
        cudaFuncSetAttribute(heads_mma, cudaFuncAttributeMaxDynamicSharedMemorySize, H_TOTAL);
        smem_set = 1;
    }

    prep_wh<<<2353, 256>>>(cw, clw, clb, bw, bb);
    prep_f<<<16384, 256>>>(feat);
    conv_tc<<<dim3(4, 128, 4), 256, SM_TOTAL>>>(cb);
    heads_mma<<<512, 256, H_TOTAL>>>();
    sel_scan<<<BATCH, 1024>>>();
    sel_collect<<<dim3(72, BATCH), 512>>>();
    sel_final<<<BATCH, 1024>>>(ihp, iwp);
    nms_mask_kernel<<<dim3(MASKW, MASKW, BATCH), 32>>>();
    final_kernel<<<BATCH, 32>>>(out);
}